// round 1
// baseline (speedup 1.0000x reference)
#include <cuda_runtime.h>
#include <math.h>

// ---------------- problem constants ----------------
#define B_   64
#define C_   384
#define HW_  256            // n = H*W
#define MTOT (B_*HW_)       // 16384
#define HEADS 8
#define DHEAD 32
#define INNER (HEADS*DHEAD) // 256
#define HID   (4*C_)        // 1536

// ---------------- device scratch (allocation-free rule) ----------------
__device__ float g_t  [MTOT*C_];     // t  [B,n,C]
__device__ float g_a  [MTOT*C_];     // LN1(t)  (reused later as final y)
__device__ float g_f  [MTOT*C_];     // LN2(t)
__device__ float g_qkv[MTOT*3*INNER];
__device__ float g_o  [MTOT*INNER];
__device__ float g_s1 [MTOT*C_];     // t + attn_out
__device__ float g_g  [MTOT*HID];    // gelu(ff1)

// ---------------- fused transpose + dual LayerNorm ----------------
// one block per (b,p) row, 384 threads (one per channel)
__global__ void ln_kernel(const float* __restrict__ x,
                          const float* __restrict__ g1, const float* __restrict__ b1,
                          const float* __restrict__ g2, const float* __restrict__ b2,
                          float* __restrict__ t, float* __restrict__ a, float* __restrict__ f)
{
    int row = blockIdx.x;            // b*n + p
    int b   = row >> 8;
    int p   = row & 255;
    int c   = threadIdx.x;           // 0..383

    float v = x[((size_t)b*C_ + c)*HW_ + p];

    __shared__ float red[12];
    __shared__ float s_mean, s_var;

    // --- mean ---
    float s = v;
    #pragma unroll
    for (int o = 16; o; o >>= 1) s += __shfl_down_sync(0xffffffffu, s, o);
    if ((c & 31) == 0) red[c >> 5] = s;
    __syncthreads();
    if (c < 32) {
        float z = (c < 12) ? red[c] : 0.f;
        #pragma unroll
        for (int o = 16; o; o >>= 1) z += __shfl_down_sync(0xffffffffu, z, o);
        if (c == 0) s_mean = z * (1.f/384.f);
    }
    __syncthreads();
    float mean = s_mean;
    float d = v - mean;

    // --- variance (population) ---
    float sq = d*d;
    #pragma unroll
    for (int o = 16; o; o >>= 1) sq += __shfl_down_sync(0xffffffffu, sq, o);
    __syncthreads();                 // protect red[] reuse
    if ((c & 31) == 0) red[c >> 5] = sq;
    __syncthreads();
    if (c < 32) {
        float z = (c < 12) ? red[c] : 0.f;
        #pragma unroll
        for (int o = 16; o; o >>= 1) z += __shfl_down_sync(0xffffffffu, z, o);
        if (c == 0) s_var = z * (1.f/384.f);
    }
    __syncthreads();
    float rstd = rsqrtf(s_var + 1e-5f);

    size_t oidx = (size_t)row*C_ + c;
    t[oidx] = v;
    float nrm = d * rstd;
    a[oidx] = nrm * g1[c] + b1[c];
    f[oidx] = nrm * g2[c] + b2[c];
}

// ---------------- tiled SGEMM, 128x128x8, 256 threads, 8x8 microtile ----------------
// C[M,N] = A[M,K] @ B[K,N]  (+bias[col]) (gelu) (+add[row,col])
// Requires M%128==0, N%128==0, K%8==0.
__global__ __launch_bounds__(256)
void sgemm_kernel(const float* __restrict__ A, const float* __restrict__ Bm,
                  float* __restrict__ C, int M, int N, int K,
                  const float* __restrict__ bias, const float* __restrict__ add,
                  int do_gelu)
{
    const int BM = 128, BN = 128, BK = 8;
    __shared__ float As[BK][BM];
    __shared__ float Bs[BK][BN];

    int tid = threadIdx.x;
    int tx  = tid & 15;      // 0..15
    int ty  = tid >> 4;      // 0..15
    int brow = blockIdx.y * BM;
    int bcol = blockIdx.x * BN;

    // A tile loader: 128 rows x 8 cols = 256 float4
    int a_row = tid >> 1;
    int a_col = (tid & 1) * 4;
    // B tile loader: 8 rows x 128 cols = 256 float4
    int b_row = tid >> 5;
    int b_col = (tid & 31) * 4;

    const float* Ab = A + (size_t)brow * K;
    const float* Bb = Bm + bcol;

    float acc[8][8];
    #pragma unroll
    for (int i = 0; i < 8; i++)
        #pragma unroll
        for (int j = 0; j < 8; j++) acc[i][j] = 0.f;

    for (int k0 = 0; k0 < K; k0 += BK) {
        float4 av = *(const float4*)(Ab + (size_t)a_row*K + k0 + a_col);
        As[a_col+0][a_row] = av.x;
        As[a_col+1][a_row] = av.y;
        As[a_col+2][a_row] = av.z;
        As[a_col+3][a_row] = av.w;
        float4 bv = *(const float4*)(Bb + (size_t)(k0 + b_row)*N + b_col);
        *(float4*)&Bs[b_row][b_col] = bv;
        __syncthreads();

        #pragma unroll
        for (int k = 0; k < BK; k++) {
            float4 a0 = *(const float4*)&As[k][ty*8 + 0];
            float4 a1 = *(const float4*)&As[k][ty*8 + 4];
            float4 b0 = *(const float4*)&Bs[k][tx*8 + 0];
            float4 b1 = *(const float4*)&Bs[k][tx*8 + 4];
            float ar[8] = {a0.x,a0.y,a0.z,a0.w,a1.x,a1.y,a1.z,a1.w};
            float br[8] = {b0.x,b0.y,b0.z,b0.w,b1.x,b1.y,b1.z,b1.w};
            #pragma unroll
            for (int i = 0; i < 8; i++)
                #pragma unroll
                for (int j = 0; j < 8; j++)
                    acc[i][j] = fmaf(ar[i], br[j], acc[i][j]);
        }
        __syncthreads();
    }

    #pragma unroll
    for (int i = 0; i < 8; i++) {
        int row = brow + ty*8 + i;
        #pragma unroll
        for (int j = 0; j < 8; j++) {
            int col = bcol + tx*8 + j;
            float v = acc[i][j];
            if (bias) v += bias[col];
            if (do_gelu) v = 0.5f * v * (1.f + erff(v * 0.70710678118654752f));
            if (add)  v += add[(size_t)row*N + col];
            C[(size_t)row*N + col] = v;
        }
    }
}

// ---------------- attention: one block per (b,h), thread i = query row ----------------
#define ATTN_SMEM ((8192 + 8192 + 961) * 4)
__global__ __launch_bounds__(256)
void attn_kernel(const float* __restrict__ qkv, const float* __restrict__ bias_table,
                 float* __restrict__ o)
{
    extern __shared__ float sm[];
    float* ksh = sm;            // [256][32]
    float* vsh = sm + 8192;     // [256][32]
    float* bsh = sm + 16384;    // [961] per-head bias column

    int b = blockIdx.x >> 3;
    int h = blockIdx.x & 7;
    int tid = threadIdx.x;

    const float* base = qkv + (size_t)b * HW_ * (3*INNER);

    for (int l = tid; l < 8192; l += 256) {
        int j = l >> 5, d = l & 31;
        ksh[l] = base[(size_t)j*(3*INNER) + INNER   + h*DHEAD + d];
        vsh[l] = base[(size_t)j*(3*INNER) + 2*INNER + h*DHEAD + d];
    }
    for (int l = tid; l < 961; l += 256) bsh[l] = bias_table[(size_t)l*HEADS + h];
    __syncthreads();

    const int i = tid;           // query index 0..255
    const float scale = 0.17677669529663688f;   // 1/sqrt(32)
    float q[DHEAD];
    const float* qp = base + (size_t)i*(3*INNER) + h*DHEAD;
    #pragma unroll
    for (int d = 0; d < DHEAD; d++) q[d] = qp[d] * scale;

    int yi = i >> 4, xi = i & 15;
    float m = -1e30f, lsum = 0.f;
    float acc[DHEAD];
    #pragma unroll
    for (int d = 0; d < DHEAD; d++) acc[d] = 0.f;

    for (int j = 0; j < HW_; j++) {
        const float* kr = ksh + j*DHEAD;
        float s = 0.f;
        #pragma unroll
        for (int d = 0; d < DHEAD; d++) s = fmaf(q[d], kr[d], s);
        int yj = j >> 4, xj = j & 15;
        s += bsh[(yi - yj + 15)*31 + (xi - xj + 15)];

        float nm = fmaxf(m, s);
        float corr = __expf(m - nm);
        float p = __expf(s - nm);
        m = nm;
        lsum = lsum * corr + p;
        const float* vr = vsh + j*DHEAD;
        #pragma unroll
        for (int d = 0; d < DHEAD; d++)
            acc[d] = fmaf(acc[d], corr, p * vr[d]);
    }

    float inv = 1.f / lsum;
    float* op = o + ((size_t)(b*HW_ + i))*INNER + h*DHEAD;
    #pragma unroll
    for (int d = 0; d < DHEAD; d++) op[d] = acc[d] * inv;
}

// ---------------- output transpose: y[B,n,C] -> out[B,C,H,W] ----------------
__global__ void transpose_out_kernel(const float* __restrict__ y, float* __restrict__ out)
{
    __shared__ float tile[32][33];
    int b  = blockIdx.z;
    int c0 = blockIdx.x * 32;
    int p0 = blockIdx.y * 32;
    const float* yb = y  + (size_t)b * HW_ * C_;
    float*       ob = out + (size_t)b * C_ * HW_;

    for (int i = threadIdx.y; i < 32; i += 8)
        tile[i][threadIdx.x] = yb[(size_t)(p0 + i)*C_ + c0 + threadIdx.x];
    __syncthreads();
    for (int i = threadIdx.y; i < 32; i += 8)
        ob[(size_t)(c0 + i)*HW_ + p0 + threadIdx.x] = tile[threadIdx.x][i];
}

// ---------------- launch ----------------
extern "C" void kernel_launch(void* const* d_in, const int* in_sizes, int n_in,
                              void* d_out, int out_size)
{
    const float* x          = (const float*)d_in[0];
    const float* ln1_g      = (const float*)d_in[1];
    const float* ln1_b      = (const float*)d_in[2];
    const float* w_qkv      = (const float*)d_in[3];
    const float* bias_table = (const float*)d_in[4];
    const float* w_out      = (const float*)d_in[5];
    const float* b_out      = (const float*)d_in[6];
    const float* ln2_g      = (const float*)d_in[7];
    const float* ln2_b      = (const float*)d_in[8];
    const float* w_ff1      = (const float*)d_in[9];
    const float* b_ff1      = (const float*)d_in[10];
    const float* w_ff2      = (const float*)d_in[11];
    const float* b_ff2      = (const float*)d_in[12];

    float *t, *a, *f, *qkv, *o, *s1, *g;
    cudaGetSymbolAddress((void**)&t,   g_t);
    cudaGetSymbolAddress((void**)&a,   g_a);
    cudaGetSymbolAddress((void**)&f,   g_f);
    cudaGetSymbolAddress((void**)&qkv, g_qkv);
    cudaGetSymbolAddress((void**)&o,   g_o);
    cudaGetSymbolAddress((void**)&s1,  g_s1);
    cudaGetSymbolAddress((void**)&g,   g_g);

    cudaFuncSetAttribute(attn_kernel, cudaFuncAttributeMaxDynamicSharedMemorySize, ATTN_SMEM);

    // 1) transpose + LN1 + LN2
    ln_kernel<<<MTOT, 384>>>(x, ln1_g, ln1_b, ln2_g, ln2_b, t, a, f);

    // 2) qkv = a @ w_qkv    [16384,384]x[384,768]
    sgemm_kernel<<<dim3(3*INNER/128, MTOT/128), 256>>>(a, w_qkv, qkv,
        MTOT, 3*INNER, C_, nullptr, nullptr, 0);

    // 3) attention
    attn_kernel<<<B_*HEADS, 256, ATTN_SMEM>>>(qkv, bias_table, o);

    // 4) s1 = t + (o @ w_out + b_out)   [16384,256]x[256,384]
    sgemm_kernel<<<dim3(C_/128, MTOT/128), 256>>>(o, w_out, s1,
        MTOT, C_, INNER, b_out, t, 0);

    // 5) g = gelu(f @ w_ff1 + b_ff1)    [16384,384]x[384,1536]
    sgemm_kernel<<<dim3(HID/128, MTOT/128), 256>>>(f, w_ff1, g,
        MTOT, HID, C_, b_ff1, nullptr, 1);

    // 6) y = s1 + (g @ w_ff2 + b_ff2)   [16384,1536]x[1536,384]  (reuse g_a for y)
    sgemm_kernel<<<dim3(C_/128, MTOT/128), 256>>>(g, w_ff2, a,
        MTOT, C_, HID, b_ff2, s1, 0);

    // 7) out[B,C,H,W] = y transposed
    transpose_out_kernel<<<dim3(C_/32, HW_/32, B_), dim3(32, 8)>>>(a, (float*)d_out);
}

// round 2
// speedup vs baseline: 1.4302x; 1.4302x over previous
#include <cuda_runtime.h>
#include <math.h>

// ---------------- problem constants ----------------
#define B_   64
#define C_   384
#define HW_  256            // n = H*W
#define MTOT (B_*HW_)       // 16384
#define HEADS 8
#define DHEAD 32
#define INNER (HEADS*DHEAD) // 256
#define HID   (4*C_)        // 1536

// ---------------- device scratch (allocation-free rule) ----------------
__device__ float g_t  [MTOT*C_];     // t  [B,n,C]
__device__ float g_a  [MTOT*C_];     // LN1(t)  (reused later as final y)
__device__ float g_f  [MTOT*C_];     // LN2(t)
__device__ float g_qkv[MTOT*3*INNER];
__device__ float g_o  [MTOT*INNER];
__device__ float g_s1 [MTOT*C_];     // t + attn_out
__device__ float g_g  [MTOT*HID];    // gelu(ff1)

// ---------------- fused transpose + dual LayerNorm ----------------
__global__ void ln_kernel(const float* __restrict__ x,
                          const float* __restrict__ g1, const float* __restrict__ b1,
                          const float* __restrict__ g2, const float* __restrict__ b2,
                          float* __restrict__ t, float* __restrict__ a, float* __restrict__ f)
{
    int row = blockIdx.x;            // b*n + p
    int b   = row >> 8;
    int p   = row & 255;
    int c   = threadIdx.x;           // 0..383

    float v = x[((size_t)b*C_ + c)*HW_ + p];

    __shared__ float red[12];
    __shared__ float s_mean, s_var;

    float s = v;
    #pragma unroll
    for (int o = 16; o; o >>= 1) s += __shfl_down_sync(0xffffffffu, s, o);
    if ((c & 31) == 0) red[c >> 5] = s;
    __syncthreads();
    if (c < 32) {
        float z = (c < 12) ? red[c] : 0.f;
        #pragma unroll
        for (int o = 16; o; o >>= 1) z += __shfl_down_sync(0xffffffffu, z, o);
        if (c == 0) s_mean = z * (1.f/384.f);
    }
    __syncthreads();
    float mean = s_mean;
    float d = v - mean;

    float sq = d*d;
    #pragma unroll
    for (int o = 16; o; o >>= 1) sq += __shfl_down_sync(0xffffffffu, sq, o);
    __syncthreads();
    if ((c & 31) == 0) red[c >> 5] = sq;
    __syncthreads();
    if (c < 32) {
        float z = (c < 12) ? red[c] : 0.f;
        #pragma unroll
        for (int o = 16; o; o >>= 1) z += __shfl_down_sync(0xffffffffu, z, o);
        if (c == 0) s_var = z * (1.f/384.f);
    }
    __syncthreads();
    float rstd = rsqrtf(s_var + 1e-5f);

    size_t oidx = (size_t)row*C_ + c;
    t[oidx] = v;
    float nrm = d * rstd;
    a[oidx] = nrm * g1[c] + b1[c];
    f[oidx] = nrm * g2[c] + b2[c];
}

// ---------------- tf32 tensor-core GEMM ----------------
// C[M,N] = A[M,K] @ B[K,N]  (+bias[col]) (gelu) (+add[row,col])
// BM=128 BN=128 BK=32, 256 threads (8 warps), warp tile 32x64 via m16n8k8.
// SMEM holds fragments in exact mma register layout -> conflict-free LDS.
__device__ __forceinline__ unsigned f2tf(float x) {
    unsigned u;
    asm("cvt.rna.tf32.f32 %0, %1;" : "=r"(u) : "f"(x));
    return u;
}

__global__ __launch_bounds__(256)
void tgemm_kernel(const float* __restrict__ A, const float* __restrict__ Bm,
                  float* __restrict__ C, int M, int N, int K,
                  const float* __restrict__ bias, const float* __restrict__ add,
                  int do_gelu)
{
    __shared__ __align__(16) unsigned AF[32*32*4];  // [chunk*8+mtile][lane] x uint4, 16KB
    __shared__ __align__(16) unsigned BF[64*32*2];  // [chunk*16+ntile][lane] x uint2, 16KB

    const int tid  = threadIdx.x;
    const int warp = tid >> 5;
    const int lane = tid & 31;
    const int g    = lane >> 2;   // group 0..7
    const int t4   = lane & 3;    // 0..3

    const int brow = blockIdx.y * 128;
    const int bcol = blockIdx.x * 128;

    const int wr = warp & 3;      // warp row 0..3 (rows wr*32)
    const int wc = warp >> 2;     // warp col 0..1 (cols wc*64)

    float acc[2][8][4];
    #pragma unroll
    for (int mi = 0; mi < 2; mi++)
        #pragma unroll
        for (int ni = 0; ni < 8; ni++)
            #pragma unroll
            for (int e = 0; e < 4; e++) acc[mi][ni][e] = 0.f;

    // prefetch registers: A 4 groups x 4 floats, B 8 groups x 2 floats
    float pa[4][4];
    float pb[8][2];

    // ---- load tile at k0 into regs ----
    auto load_regs = [&](int k0) {
        #pragma unroll
        for (int q = 0; q < 4; q++) {
            int idx = warp*4 + q;              // 0..31
            int ch  = idx >> 3;                // chunk 0..3
            int mt  = idx & 7;                 // mtile 0..7
            int r0  = brow + mt*16 + g;
            int kk  = k0 + ch*8 + t4;
            pa[q][0] = A[(size_t)r0*K + kk];
            pa[q][1] = A[(size_t)(r0+8)*K + kk];
            pa[q][2] = A[(size_t)r0*K + kk + 4];
            pa[q][3] = A[(size_t)(r0+8)*K + kk + 4];
        }
        #pragma unroll
        for (int q = 0; q < 8; q++) {
            int idx = warp*8 + q;              // 0..63
            int ch  = idx >> 4;                // chunk 0..3
            int nt  = idx & 15;                // ntile 0..15
            int col = bcol + nt*8 + g;
            int kk  = k0 + ch*8 + t4;
            pb[q][0] = Bm[(size_t)kk*N + col];
            pb[q][1] = Bm[(size_t)(kk+4)*N + col];
        }
    };

    auto store_smem = [&]() {
        #pragma unroll
        for (int q = 0; q < 4; q++) {
            int idx = warp*4 + q;
            uint4 u;
            u.x = f2tf(pa[q][0]); u.y = f2tf(pa[q][1]);
            u.z = f2tf(pa[q][2]); u.w = f2tf(pa[q][3]);
            *(uint4*)&AF[(idx*32 + lane)*4] = u;
        }
        #pragma unroll
        for (int q = 0; q < 8; q++) {
            int idx = warp*8 + q;
            uint2 v;
            v.x = f2tf(pb[q][0]); v.y = f2tf(pb[q][1]);
            *(uint2*)&BF[(idx*32 + lane)*2] = v;
        }
    };

    auto compute = [&]() {
        #pragma unroll
        for (int ch = 0; ch < 4; ch++) {
            uint4 a[2];
            #pragma unroll
            for (int mi = 0; mi < 2; mi++)
                a[mi] = *(const uint4*)&AF[((ch*8 + wr*2 + mi)*32 + lane)*4];
            uint2 b[8];
            #pragma unroll
            for (int ni = 0; ni < 8; ni++)
                b[ni] = *(const uint2*)&BF[((ch*16 + wc*8 + ni)*32 + lane)*2];
            #pragma unroll
            for (int mi = 0; mi < 2; mi++)
                #pragma unroll
                for (int ni = 0; ni < 8; ni++) {
                    asm volatile(
                        "mma.sync.aligned.m16n8k8.row.col.f32.tf32.tf32.f32 "
                        "{%0,%1,%2,%3},{%4,%5,%6,%7},{%8,%9},{%0,%1,%2,%3};"
                        : "+f"(acc[mi][ni][0]), "+f"(acc[mi][ni][1]),
                          "+f"(acc[mi][ni][2]), "+f"(acc[mi][ni][3])
                        : "r"(a[mi].x), "r"(a[mi].y), "r"(a[mi].z), "r"(a[mi].w),
                          "r"(b[ni].x), "r"(b[ni].y));
                }
        }
    };

    load_regs(0);
    store_smem();
    __syncthreads();

    const int nkt = K >> 5;
    for (int kt = 1; kt < nkt; kt++) {
        load_regs(kt*32);
        compute();
        __syncthreads();
        store_smem();
        __syncthreads();
    }
    compute();

    // ---- epilogue ----
    #pragma unroll
    for (int mi = 0; mi < 2; mi++) {
        int r0 = brow + wr*32 + mi*16 + g;
        #pragma unroll
        for (int ni = 0; ni < 8; ni++) {
            int col = bcol + wc*64 + ni*8 + 2*t4;
            float v0 = acc[mi][ni][0];
            float v1 = acc[mi][ni][1];
            float v2 = acc[mi][ni][2];
            float v3 = acc[mi][ni][3];
            if (bias) {
                float bz0 = bias[col], bz1 = bias[col+1];
                v0 += bz0; v1 += bz1; v2 += bz0; v3 += bz1;
            }
            if (do_gelu) {
                v0 = 0.5f*v0*(1.f + erff(v0*0.70710678118654752f));
                v1 = 0.5f*v1*(1.f + erff(v1*0.70710678118654752f));
                v2 = 0.5f*v2*(1.f + erff(v2*0.70710678118654752f));
                v3 = 0.5f*v3*(1.f + erff(v3*0.70710678118654752f));
            }
            if (add) {
                float2 a0 = *(const float2*)&add[(size_t)r0*N + col];
                float2 a1 = *(const float2*)&add[(size_t)(r0+8)*N + col];
                v0 += a0.x; v1 += a0.y; v2 += a1.x; v3 += a1.y;
            }
            *(float2*)&C[(size_t)r0*N + col]     = make_float2(v0, v1);
            *(float2*)&C[(size_t)(r0+8)*N + col] = make_float2(v2, v3);
        }
    }
}

// ---------------- attention: one block per (b,h), thread i = query row ----------------
#define ATTN_SMEM ((8192 + 8192 + 961) * 4)
__global__ __launch_bounds__(256)
void attn_kernel(const float* __restrict__ qkv, const float* __restrict__ bias_table,
                 float* __restrict__ o)
{
    extern __shared__ float sm[];
    float* ksh = sm;            // [256][32]
    float* vsh = sm + 8192;     // [256][32]
    float* bsh = sm + 16384;    // [961] per-head bias column

    int b = blockIdx.x >> 3;
    int h = blockIdx.x & 7;
    int tid = threadIdx.x;

    const float* base = qkv + (size_t)b * HW_ * (3*INNER);

    for (int l = tid; l < 8192; l += 256) {
        int j = l >> 5, d = l & 31;
        ksh[l] = base[(size_t)j*(3*INNER) + INNER   + h*DHEAD + d];
        vsh[l] = base[(size_t)j*(3*INNER) + 2*INNER + h*DHEAD + d];
    }
    for (int l = tid; l < 961; l += 256) bsh[l] = bias_table[(size_t)l*HEADS + h];
    __syncthreads();

    const int i = tid;
    const float scale = 0.17677669529663688f;   // 1/sqrt(32)
    float q[DHEAD];
    const float* qp = base + (size_t)i*(3*INNER) + h*DHEAD;
    #pragma unroll
    for (int d = 0; d < DHEAD; d++) q[d] = qp[d] * scale;

    int yi = i >> 4, xi = i & 15;
    float m = -1e30f, lsum = 0.f;
    float acc[DHEAD];
    #pragma unroll
    for (int d = 0; d < DHEAD; d++) acc[d] = 0.f;

    for (int j = 0; j < HW_; j++) {
        const float* kr = ksh + j*DHEAD;
        float s = 0.f;
        #pragma unroll
        for (int d = 0; d < DHEAD; d++) s = fmaf(q[d], kr[d], s);
        int yj = j >> 4, xj = j & 15;
        s += bsh[(yi - yj + 15)*31 + (xi - xj + 15)];

        float nm = fmaxf(m, s);
        float corr = __expf(m - nm);
        float p = __expf(s - nm);
        m = nm;
        lsum = lsum * corr + p;
        const float* vr = vsh + j*DHEAD;
        #pragma unroll
        for (int d = 0; d < DHEAD; d++)
            acc[d] = fmaf(acc[d], corr, p * vr[d]);
    }

    float inv = 1.f / lsum;
    float* op = o + ((size_t)(b*HW_ + i))*INNER + h*DHEAD;
    #pragma unroll
    for (int d = 0; d < DHEAD; d++) op[d] = acc[d] * inv;
}

// ---------------- output transpose: y[B,n,C] -> out[B,C,H,W] ----------------
__global__ void transpose_out_kernel(const float* __restrict__ y, float* __restrict__ out)
{
    __shared__ float tile[32][33];
    int b  = blockIdx.z;
    int c0 = blockIdx.x * 32;
    int p0 = blockIdx.y * 32;
    const float* yb = y  + (size_t)b * HW_ * C_;
    float*       ob = out + (size_t)b * C_ * HW_;

    for (int i = threadIdx.y; i < 32; i += 8)
        tile[i][threadIdx.x] = yb[(size_t)(p0 + i)*C_ + c0 + threadIdx.x];
    __syncthreads();
    for (int i = threadIdx.y; i < 32; i += 8)
        ob[(size_t)(c0 + i)*HW_ + p0 + threadIdx.x] = tile[threadIdx.x][i];
}

// ---------------- launch ----------------
extern "C" void kernel_launch(void* const* d_in, const int* in_sizes, int n_in,
                              void* d_out, int out_size)
{
    const float* x          = (const float*)d_in[0];
    const float* ln1_g      = (const float*)d_in[1];
    const float* ln1_b      = (const float*)d_in[2];
    const float* w_qkv      = (const float*)d_in[3];
    const float* bias_table = (const float*)d_in[4];
    const float* w_out      = (const float*)d_in[5];
    const float* b_out      = (const float*)d_in[6];
    const float* ln2_g      = (const float*)d_in[7];
    const float* ln2_b      = (const float*)d_in[8];
    const float* w_ff1      = (const float*)d_in[9];
    const float* b_ff1      = (const float*)d_in[10];
    const float* w_ff2      = (const float*)d_in[11];
    const float* b_ff2      = (const float*)d_in[12];

    float *t, *a, *f, *qkv, *o, *s1, *g;
    cudaGetSymbolAddress((void**)&t,   g_t);
    cudaGetSymbolAddress((void**)&a,   g_a);
    cudaGetSymbolAddress((void**)&f,   g_f);
    cudaGetSymbolAddress((void**)&qkv, g_qkv);
    cudaGetSymbolAddress((void**)&o,   g_o);
    cudaGetSymbolAddress((void**)&s1,  g_s1);
    cudaGetSymbolAddress((void**)&g,   g_g);

    cudaFuncSetAttribute(attn_kernel, cudaFuncAttributeMaxDynamicSharedMemorySize, ATTN_SMEM);

    // 1) transpose + LN1 + LN2
    ln_kernel<<<MTOT, 384>>>(x, ln1_g, ln1_b, ln2_g, ln2_b, t, a, f);

    // 2) qkv = a @ w_qkv    [16384,384]x[384,768]
    tgemm_kernel<<<dim3(3*INNER/128, MTOT/128), 256>>>(a, w_qkv, qkv,
        MTOT, 3*INNER, C_, nullptr, nullptr, 0);

    // 3) attention
    attn_kernel<<<B_*HEADS, 256, ATTN_SMEM>>>(qkv, bias_table, o);

    // 4) s1 = t + (o @ w_out + b_out)   [16384,256]x[256,384]
    tgemm_kernel<<<dim3(C_/128, MTOT/128), 256>>>(o, w_out, s1,
        MTOT, C_, INNER, b_out, t, 0);

    // 5) g = gelu(f @ w_ff1 + b_ff1)    [16384,384]x[384,1536]
    tgemm_kernel<<<dim3(HID/128, MTOT/128), 256>>>(f, w_ff1, g,
        MTOT, HID, C_, b_ff1, nullptr, 1);

    // 6) y = s1 + (g @ w_ff2 + b_ff2)   [16384,1536]x[1536,384]  (reuse g_a for y)
    tgemm_kernel<<<dim3(C_/128, MTOT/128), 256>>>(g, w_ff2, a,
        MTOT, C_, HID, b_ff2, s1, 0);

    // 7) out[B,C,H,W] = y transposed
    transpose_out_kernel<<<dim3(C_/32, HW_/32, B_), dim3(32, 8)>>>(a, (float*)d_out);
}